// round 1
// baseline (speedup 1.0000x reference)
#include <cuda_runtime.h>
#include <math.h>

// Problem constants (match reference)
#define NSd   12
#define NCd   4
#define Td    32
#define Nd    16            // NS + NC
#define NZd   512           // T * N
#define NEQ   384           // NS * T
#define NIN   128           // T * NC (per side)
#define DAMPv 1e-4f

// Shared-memory working set per batch (one CTA per batch), ~74.5 KB
struct SmemLayout {
    float M[12 * 16];       // [A | B], row-major: M[i][j], i<12, j<16
    float MtM[16 * 16];     // M^T M (constant)
    float x0[12];
    float z[NZd];
    float Qd[NZd];
    float cd[NZd];
    float g[NZd];           // gradient -> y -> dz (in place)
    float lamE[NEQ];
    float lamU[NIN];
    float lamL[NIN];
    float lo[NIN];
    float up[NIN];
    float Yv[NEQ];          // rho*r + lamE
    float invd[Td * 16];    // 1 / L[k][k] per block
    float L[Td * 16 * 16];  // block Cholesky factors (lower; diag NOT stored, use invd)
    float W[Td * 12 * 16];  // off-diagonal solved blocks W_t = C L_{t-1}^{-T} (rows >=12 are zero)
};

__global__ __launch_bounds__(256, 1)
void mpc_kernel(const float* __restrict__ x0g, const float* __restrict__ Qg,
                const float* __restrict__ cg,  const float* __restrict__ Ag,
                const float* __restrict__ Bg,  const float* __restrict__ log_,
                const float* __restrict__ upg, float* __restrict__ out, int NB)
{
    extern __shared__ float smraw[];
    SmemLayout* S = reinterpret_cast<SmemLayout*>(smraw);
    const int b   = blockIdx.x;
    const int tid = threadIdx.x;
    const int ii  = tid >> 4;     // matrix row for 16x16 ops
    const int jj  = tid & 15;     // matrix col

    // ---------------- load inputs ----------------
    for (int i = tid; i < NZd; i += 256) {
        S->z[i]  = 0.f;
        S->Qd[i] = Qg[b * NZd + i];
        S->cd[i] = cg[b * NZd + i];
    }
    for (int i = tid; i < NEQ; i += 256) S->lamE[i] = 0.f;
    for (int i = tid; i < NIN; i += 256) {
        S->lamU[i] = 0.f; S->lamL[i] = 0.f;
        S->lo[i] = log_[b * NIN + i];
        S->up[i] = upg[b * NIN + i];
    }
    if (tid < 192) {
        int r = tid / 16, cc = tid % 16;
        S->M[tid] = (cc < 12) ? Ag[r * 12 + cc] : Bg[r * 4 + (cc - 12)];
    }
    if (tid < 12) S->x0[tid] = x0g[b * 12 + tid];
    __syncthreads();

    // ---------------- MtM = M^T M (constant) ----------------
    {
        float acc = 0.f;
        #pragma unroll
        for (int k = 0; k < 12; ++k) acc += S->M[k * 16 + ii] * S->M[k * 16 + jj];
        S->MtM[ii * 16 + jj] = acc;
    }

    // ---------------- initial z: x_t = A^t x0, u = 0 ----------------
    if (tid < 12) S->z[tid] = S->x0[tid];
    for (int t = 0; t < Td - 1; ++t) {
        __syncthreads();
        if (tid < 12) {
            float acc = 0.f;
            #pragma unroll
            for (int j = 0; j < 12; ++j) acc += S->M[tid * 16 + j] * S->z[t * 16 + j];
            S->z[(t + 1) * 16 + tid] = acc;
        }
    }

    float rho = 1.f;
    for (int al = 0; al < 3; ++al) {
        for (int nt = 0; nt < 3; ++nt) {
            __syncthreads();
            // ---- Yv = rho * r + lamE ----
            for (int idx = tid; idx < NEQ; idx += 256) {
                int t = idx / 12, i = idx % 12;
                float r;
                if (t == 0) r = S->z[i] - S->x0[i];
                else {
                    float acc = S->z[t * 16 + i];
                    const float* zp = &S->z[(t - 1) * 16];
                    const float* Mr = &S->M[i * 16];
                    #pragma unroll
                    for (int k = 0; k < 16; ++k) acc -= Mr[k] * zp[k];
                    r = acc;
                }
                S->Yv[idx] = rho * r + S->lamE[idx];
            }
            __syncthreads();
            // ---- gradient ----
            for (int idx = tid; idx < NZd; idx += 256) {
                int t = idx >> 4, i = idx & 15;
                float gv = S->Qd[idx] * S->z[idx] + S->cd[idx];
                if (i < 12) gv += S->Yv[t * 12 + i];
                if (t < Td - 1) {
                    const float* Yn = &S->Yv[(t + 1) * 12];
                    float acc = 0.f;
                    #pragma unroll
                    for (int k = 0; k < 12; ++k) acc += S->M[k * 16 + i] * Yn[k];
                    gv -= acc;
                }
                if (i >= 12) {
                    int uidx = t * 4 + (i - 12);
                    float uv = S->z[idx];
                    float su = fmaxf(rho * (uv - S->up[uidx]) + S->lamU[uidx], 0.f);
                    float sl = fmaxf(rho * (S->lo[uidx] - uv) + S->lamL[uidx], 0.f);
                    gv += su - sl;
                }
                S->g[idx] = gv;
            }
            __syncthreads();

            // ---- block-tridiagonal Cholesky factorization over t ----
            for (int t = 0; t < Td; ++t) {
                float* Lt = &S->L[t * 256];
                if (t > 0) {
                    // W_t = C * L_{t-1}^{-T}, C = -rho*[M;0]. 12 threads, register rows.
                    if (tid < 12) {
                        const float* Lp  = &S->L[(t - 1) * 256];
                        const float* ivp = &S->invd[(t - 1) * 16];
                        float Wr[16];
                        #pragma unroll
                        for (int j = 0; j < 16; ++j) {
                            float acc = -rho * S->M[tid * 16 + j];
                            #pragma unroll
                            for (int k = 0; k < 16; ++k)
                                if (k < j) acc -= Wr[k] * Lp[j * 16 + k];
                            Wr[j] = acc * ivp[j];
                        }
                        float* Wt = &S->W[t * 192 + tid * 16];
                        #pragma unroll
                        for (int j = 0; j < 16; ++j) Wt[j] = Wr[j];
                    }
                    __syncthreads();
                }
                // build P_t = D_t - W_t W_t^T (lower triangle only)
                if (jj <= ii) {
                    float v = (t < Td - 1) ? rho * S->MtM[ii * 16 + jj] : 0.f;
                    if (ii == jj) {
                        v += S->Qd[t * 16 + ii] + DAMPv;
                        if (ii < 12) v += rho;
                        else {
                            int uidx = t * 4 + (ii - 12);
                            float uv = S->z[t * 16 + ii];
                            if (rho * (uv - S->up[uidx]) + S->lamU[uidx] > 0.f) v += rho;
                            if (rho * (S->lo[uidx] - uv) + S->lamL[uidx] > 0.f) v += rho;
                        }
                    }
                    if (t > 0 && ii < 12 && jj < 12) {
                        const float* Wi = &S->W[t * 192 + ii * 16];
                        const float* Wj = &S->W[t * 192 + jj * 16];
                        float acc = 0.f;
                        #pragma unroll
                        for (int k = 0; k < 16; ++k) acc += Wi[k] * Wj[k];
                        v -= acc;
                    }
                    Lt[ii * 16 + jj] = v;
                }
                // in-place Cholesky (2 bar.sync per column; diagonal stored only as invd)
                for (int k = 0; k < 16; ++k) {
                    __syncthreads();
                    if (jj == k && ii >= k) {
                        float inv = 1.0f / sqrtf(Lt[k * 16 + k]);  // safe: [k][k] never overwritten here
                        if (ii == k) S->invd[t * 16 + k] = inv;
                        else         Lt[ii * 16 + k] *= inv;
                    }
                    __syncthreads();
                    if (ii > k && jj > k && jj <= ii)
                        Lt[ii * 16 + jj] -= Lt[ii * 16 + k] * Lt[jj * 16 + k];
                }
                __syncthreads();
            }

            // ---- substitution: warp 0 only, warp-synchronous (no bar.sync) ----
            if (tid < 32) {
                const int lane = tid;
                // forward: L y = g
                for (int t = 0; t < Td; ++t) {
                    float bval = (lane < 16) ? S->g[t * 16 + lane] : 0.f;
                    if (t > 0 && lane < 12) {
                        const float* Wt = &S->W[t * 192 + lane * 16];
                        const float* yp = &S->g[(t - 1) * 16];
                        #pragma unroll
                        for (int k = 0; k < 16; ++k) bval -= Wt[k] * yp[k];
                    }
                    const float* Lt = &S->L[t * 256];
                    const float* iv = &S->invd[t * 16];
                    #pragma unroll
                    for (int i2 = 0; i2 < 16; ++i2) {
                        float v = __shfl_sync(0xffffffffu, bval, i2) * iv[i2];
                        if (lane == i2) bval = v;
                        else if (lane > i2 && lane < 16) bval -= Lt[lane * 16 + i2] * v;
                    }
                    if (lane < 16) S->g[t * 16 + lane] = bval;
                    __syncwarp();
                }
                // backward: L^T dz = y  (plus W^{T} coupling)
                for (int t = Td - 1; t >= 0; --t) {
                    float bval = (lane < 16) ? S->g[t * 16 + lane] : 0.f;
                    if (t < Td - 1 && lane < 16) {
                        const float* Wn  = &S->W[(t + 1) * 192];
                        const float* dzn = &S->g[(t + 1) * 16];
                        #pragma unroll
                        for (int k = 0; k < 12; ++k) bval -= Wn[k * 16 + lane] * dzn[k];
                    }
                    const float* Lt = &S->L[t * 256];
                    const float* iv = &S->invd[t * 16];
                    #pragma unroll
                    for (int i2 = 15; i2 >= 0; --i2) {
                        float v = __shfl_sync(0xffffffffu, bval, i2) * iv[i2];
                        if (lane == i2) bval = v;
                        else if (lane < i2) bval -= Lt[i2 * 16 + lane] * v;
                    }
                    if (lane < 16) S->g[t * 16 + lane] = bval;
                    __syncwarp();
                }
            }
            __syncthreads();
            // ---- z -= dz ----
            for (int idx = tid; idx < NZd; idx += 256) S->z[idx] -= S->g[idx];
        } // newton

        // ---- multiplier updates ----
        __syncthreads();
        for (int idx = tid; idx < NEQ; idx += 256) {
            int t = idx / 12, i = idx % 12;
            float r;
            if (t == 0) r = S->z[i] - S->x0[i];
            else {
                float acc = S->z[t * 16 + i];
                const float* zp = &S->z[(t - 1) * 16];
                const float* Mr = &S->M[i * 16];
                #pragma unroll
                for (int k = 0; k < 16; ++k) acc -= Mr[k] * zp[k];
                r = acc;
            }
            S->lamE[idx] += rho * r;
        }
        for (int idx = tid; idx < NIN; idx += 256) {
            int t = idx >> 2, j = idx & 3;
            float uv = S->z[t * 16 + 12 + j];
            S->lamU[idx] = fmaxf(S->lamU[idx] + rho * (uv - S->up[idx]), 0.f);
            S->lamL[idx] = fmaxf(S->lamL[idx] + rho * (S->lo[idx] - uv), 0.f);
        }
        rho = fminf(rho * 10.f, 100.f);
    } // al

    __syncthreads();
    // ---------------- outputs: x then u, each contiguous ----------------
    for (int idx = tid; idx < NEQ; idx += 256) {          // x: [NB, T, NS]
        int t = idx / 12, i = idx % 12;
        out[b * (Td * NSd) + idx] = S->z[t * 16 + i];
    }
    for (int idx = tid; idx < NIN; idx += 256) {          // u: [NB, T, NC]
        int t = idx >> 2, j = idx & 3;
        out[NB * (Td * NSd) + b * (Td * NCd) + idx] = S->z[t * 16 + 12 + j];
    }
}

extern "C" void kernel_launch(void* const* d_in, const int* in_sizes, int n_in,
                              void* d_out, int out_size)
{
    const float* x0 = (const float*)d_in[0];
    const float* Q  = (const float*)d_in[1];
    const float* c  = (const float*)d_in[2];
    const float* A  = (const float*)d_in[3];
    const float* B  = (const float*)d_in[4];
    const float* lo = (const float*)d_in[5];
    const float* up = (const float*)d_in[6];
    float* out = (float*)d_out;

    int NB = in_sizes[0] / NSd;   // 64
    size_t smem = sizeof(SmemLayout);
    cudaFuncSetAttribute(mpc_kernel, cudaFuncAttributeMaxDynamicSharedMemorySize, (int)smem);
    mpc_kernel<<<NB, 256, smem>>>(x0, Q, c, A, B, lo, up, out, NB);
}